// round 1
// baseline (speedup 1.0000x reference)
#include <cuda_runtime.h>
#include <math.h>

#define BB 8
#define TT 512
#define CC 1024
#define HH 16
#define EE 64
#define LL 2048

// Scratch (allocation-free rule: __device__ globals)
__device__ float g_q[BB*HH*TT*EE];   // [B,H,T,E]
__device__ float g_k[BB*HH*TT*EE];
__device__ float g_v[BB*HH*TT*EE];
__device__ float g_y[BB*TT*CC];      // [B,T,C] attention output

// ---------------------------------------------------------------------------
// QKV GEMM: X[4096,1024] @ Wqkv[1024,3072] + b  -> split into g_q/g_k/g_v
// 128x128x16 tile, 256 threads, 8x8 microkernel.
// ---------------------------------------------------------------------------
__global__ __launch_bounds__(256) void qkv_gemm_kernel(
    const float* __restrict__ X, const float* __restrict__ W,
    const float* __restrict__ bias)
{
    __shared__ float As[16][132];   // transposed A tile [k][m], padded
    __shared__ float Bs[16][128];   // [k][n]

    const int tid = threadIdx.x;
    const int m0 = blockIdx.y * 128;
    const int n0 = blockIdx.x * 128;
    const int tm = tid >> 4, tn = tid & 15;

    float acc[8][8];
    #pragma unroll
    for (int i = 0; i < 8; i++)
        #pragma unroll
        for (int j = 0; j < 8; j++) acc[i][j] = 0.f;

    for (int k0 = 0; k0 < 1024; k0 += 16) {
        float4 areg[2], breg[2];
        #pragma unroll
        for (int ii = 0; ii < 2; ii++) {
            int f = ii * 256 + tid;           // 0..511
            int ar = f >> 2, ae = (f & 3) << 2;
            areg[ii] = *(const float4*)&X[(m0 + ar) * 1024 + k0 + ae];
            int br = f >> 5, bc = (f & 31) << 2;
            breg[ii] = *(const float4*)&W[(k0 + br) * 3072 + n0 + bc];
        }
        __syncthreads();
        #pragma unroll
        for (int ii = 0; ii < 2; ii++) {
            int f = ii * 256 + tid;
            int ar = f >> 2, ae = (f & 3) << 2;
            As[ae + 0][ar] = areg[ii].x;
            As[ae + 1][ar] = areg[ii].y;
            As[ae + 2][ar] = areg[ii].z;
            As[ae + 3][ar] = areg[ii].w;
            int br = f >> 5, bc = (f & 31) << 2;
            *(float4*)&Bs[br][bc] = breg[ii];
        }
        __syncthreads();
        #pragma unroll
        for (int k = 0; k < 16; k++) {
            float a[8], b[8];
            *(float4*)&a[0] = *(const float4*)&As[k][tm * 8];
            *(float4*)&a[4] = *(const float4*)&As[k][tm * 8 + 4];
            *(float4*)&b[0] = *(const float4*)&Bs[k][tn * 8];
            *(float4*)&b[4] = *(const float4*)&Bs[k][tn * 8 + 4];
            #pragma unroll
            for (int i = 0; i < 8; i++)
                #pragma unroll
                for (int j = 0; j < 8; j++) acc[i][j] += a[i] * b[j];
        }
    }

    // Epilogue: n -> (part, h, e); m -> (b, t); write head layout [B,H,T,E]
    #pragma unroll
    for (int j = 0; j < 8; j++) {
        int n = n0 + tn * 8 + j;
        int part = n >> 10;
        int within = n & 1023;
        int h = within >> 6;
        int e = within & 63;
        float bv = bias[n];
        float* dst = (part == 0) ? g_q : (part == 1) ? g_k : g_v;
        #pragma unroll
        for (int i = 0; i < 8; i++) {
            int m = m0 + tm * 8 + i;
            int b = m >> 9;
            int t = m & 511;
            dst[(((b * HH) + h) * TT + t) * EE + e] = acc[i][j] + bv;
        }
    }
}

// ---------------------------------------------------------------------------
// Output projection GEMM: g_y[4096,1024] @ Wproj[1024,1024] + b -> out
// ---------------------------------------------------------------------------
__global__ __launch_bounds__(256) void proj_gemm_kernel(
    const float* __restrict__ W, const float* __restrict__ bias,
    float* __restrict__ out)
{
    __shared__ float As[16][132];
    __shared__ float Bs[16][128];

    const int tid = threadIdx.x;
    const int m0 = blockIdx.y * 128;
    const int n0 = blockIdx.x * 128;
    const int tm = tid >> 4, tn = tid & 15;

    float acc[8][8];
    #pragma unroll
    for (int i = 0; i < 8; i++)
        #pragma unroll
        for (int j = 0; j < 8; j++) acc[i][j] = 0.f;

    for (int k0 = 0; k0 < 1024; k0 += 16) {
        float4 areg[2], breg[2];
        #pragma unroll
        for (int ii = 0; ii < 2; ii++) {
            int f = ii * 256 + tid;
            int ar = f >> 2, ae = (f & 3) << 2;
            areg[ii] = *(const float4*)&g_y[(m0 + ar) * 1024 + k0 + ae];
            int br = f >> 5, bc = (f & 31) << 2;
            breg[ii] = *(const float4*)&W[(k0 + br) * 1024 + n0 + bc];
        }
        __syncthreads();
        #pragma unroll
        for (int ii = 0; ii < 2; ii++) {
            int f = ii * 256 + tid;
            int ar = f >> 2, ae = (f & 3) << 2;
            As[ae + 0][ar] = areg[ii].x;
            As[ae + 1][ar] = areg[ii].y;
            As[ae + 2][ar] = areg[ii].z;
            As[ae + 3][ar] = areg[ii].w;
            int br = f >> 5, bc = (f & 31) << 2;
            *(float4*)&Bs[br][bc] = breg[ii];
        }
        __syncthreads();
        #pragma unroll
        for (int k = 0; k < 16; k++) {
            float a[8], b[8];
            *(float4*)&a[0] = *(const float4*)&As[k][tm * 8];
            *(float4*)&a[4] = *(const float4*)&As[k][tm * 8 + 4];
            *(float4*)&b[0] = *(const float4*)&Bs[k][tn * 8];
            *(float4*)&b[4] = *(const float4*)&Bs[k][tn * 8 + 4];
            #pragma unroll
            for (int i = 0; i < 8; i++)
                #pragma unroll
                for (int j = 0; j < 8; j++) acc[i][j] += a[i] * b[j];
        }
    }

    #pragma unroll
    for (int i = 0; i < 8; i++) {
        int m = m0 + tm * 8 + i;
        #pragma unroll
        for (int j = 0; j < 8; j++) {
            int n = n0 + tn * 8 + j;
            out[m * 1024 + n] = acc[i][j] + bias[n];
        }
    }
}

// ---------------------------------------------------------------------------
// Flash attention: per (b,h) 64-query block, streaming over 64-key tiles.
// Cache tiles (32) unmasked; new tiles causal; only last tile diagonal-masked.
// ---------------------------------------------------------------------------
#define ATT_SMEM_FLOATS (4096*4 + 64*65 + 256*2 + 64*3)   // 21248 floats
#define ATT_SMEM_BYTES  (ATT_SMEM_FLOATS * 4)             // 84992 bytes

__global__ __launch_bounds__(256) void attn_kernel(
    const float* __restrict__ k_cache, const float* __restrict__ v_cache)
{
    extern __shared__ float sm[];
    float* Qt      = sm;               // [e][i]  64x64 (pre-scaled by 1/8)
    float* Kt      = Qt + 4096;        // [e][j]  64x64
    float* Vs      = Kt + 4096;        // [j][e]  64x64
    float* Ss      = Vs + 4096;        // [i][j]  64x65 (pad 1)
    float* Pt      = Ss + 64 * 65;     // [j][i]  64x64
    float* red_m   = Pt + 4096;        // [4][64]
    float* red_l   = red_m + 256;      // [4][64]
    float* m_s     = red_l + 256;      // [64]
    float* l_s     = m_s + 64;         // [64]
    float* alpha_s = l_s + 64;         // [64]

    const int tid = threadIdx.x;
    const int bh  = blockIdx.y;                 // b*16 + h
    const int m0  = blockIdx.x * 64;
    const int tc  = tid & 15, tr = tid >> 4;    // 16x16 thread grid, 4x4 frags

    const float* qptr = g_q + (bh * TT + m0) * EE;
    const float* knew = g_k + bh * TT * EE;
    const float* vnew = g_v + bh * TT * EE;
    const float* kc   = k_cache + (size_t)bh * LL * EE;
    const float* vc   = v_cache + (size_t)bh * LL * EE;

    // Load Q transposed + pre-scale by 1/sqrt(E)=0.125
    #pragma unroll
    for (int ii = 0; ii < 4; ii++) {
        int f = ii * 256 + tid;
        int r = f >> 4, e0 = (f & 15) << 2;
        float4 v = *(const float4*)&qptr[r * EE + e0];
        Qt[(e0 + 0) * 64 + r] = v.x * 0.125f;
        Qt[(e0 + 1) * 64 + r] = v.y * 0.125f;
        Qt[(e0 + 2) * 64 + r] = v.z * 0.125f;
        Qt[(e0 + 3) * 64 + r] = v.w * 0.125f;
    }
    if (tid < 64) { m_s[tid] = -1e30f; l_s[tid] = 0.f; }

    float o[4][4];
    #pragma unroll
    for (int i = 0; i < 4; i++)
        #pragma unroll
        for (int j = 0; j < 4; j++) o[i][j] = 0.f;

    const int n_tiles = 32 + (m0 >> 6) + 1;

    for (int kt = 0; kt < n_tiles; kt++) {
        const float *ksrc, *vsrc;
        if (kt < 32) { ksrc = kc + kt * 64 * EE;           vsrc = vc + kt * 64 * EE; }
        else         { ksrc = knew + (kt - 32) * 64 * EE;  vsrc = vnew + (kt - 32) * 64 * EE; }

        float4 kreg[4], vreg[4];
        #pragma unroll
        for (int ii = 0; ii < 4; ii++) {
            int f = ii * 256 + tid;
            int r = f >> 4, e0 = (f & 15) << 2;
            kreg[ii] = *(const float4*)&ksrc[r * EE + e0];
            vreg[ii] = *(const float4*)&vsrc[r * EE + e0];
        }
        __syncthreads();   // prev iteration done with Kt/Vs/Ss/Pt
        #pragma unroll
        for (int ii = 0; ii < 4; ii++) {
            int f = ii * 256 + tid;
            int r = f >> 4, e0 = (f & 15) << 2;
            Kt[(e0 + 0) * 64 + r] = kreg[ii].x;
            Kt[(e0 + 1) * 64 + r] = kreg[ii].y;
            Kt[(e0 + 2) * 64 + r] = kreg[ii].z;
            Kt[(e0 + 3) * 64 + r] = kreg[ii].w;
            *(float4*)&Vs[r * 64 + e0] = vreg[ii];
        }
        __syncthreads();

        // S tile: s[qi][qj] = sum_e Qt[e][tr*4+qi] * Kt[e][tc*4+qj]
        float s[4][4];
        #pragma unroll
        for (int i = 0; i < 4; i++)
            #pragma unroll
            for (int j = 0; j < 4; j++) s[i][j] = 0.f;
        #pragma unroll 8
        for (int e = 0; e < 64; e++) {
            float4 qv = *(const float4*)&Qt[e * 64 + tr * 4];
            float4 kv = *(const float4*)&Kt[e * 64 + tc * 4];
            float qa[4] = {qv.x, qv.y, qv.z, qv.w};
            float ka[4] = {kv.x, kv.y, kv.z, kv.w};
            #pragma unroll
            for (int i = 0; i < 4; i++)
                #pragma unroll
                for (int j = 0; j < 4; j++) s[i][j] += qa[i] * ka[j];
        }

        const bool diag = (kt == n_tiles - 1);
        #pragma unroll
        for (int i = 0; i < 4; i++)
            #pragma unroll
            for (int j = 0; j < 4; j++) {
                float v = s[i][j];
                if (diag && (tc * 4 + j) > (tr * 4 + i)) v = -1e30f;
                Ss[(tr * 4 + i) * 65 + tc * 4 + j] = v;
            }
        __syncthreads();

        // Online softmax: 4 threads per row (g = tid/64), 16 cols each
        const int r = tid & 63, g = tid >> 6;
        const float* srow = &Ss[r * 65 + g * 16];
        float mt = srow[0];
        #pragma unroll
        for (int jj = 1; jj < 16; jj++) mt = fmaxf(mt, srow[jj]);
        red_m[g * 64 + r] = mt;
        __syncthreads();

        float mold = m_s[r];
        float mnew = fmaxf(fmaxf(red_m[r], red_m[64 + r]),
                           fmaxf(red_m[128 + r], red_m[192 + r]));
        mnew = fmaxf(mnew, mold);
        float lsum = 0.f;
        #pragma unroll
        for (int jj = 0; jj < 16; jj++) {
            float p = __expf(srow[jj] - mnew);
            Pt[(g * 16 + jj) * 64 + r] = p;
            lsum += p;
        }
        red_l[g * 64 + r] = lsum;
        if (g == 0) { alpha_s[r] = __expf(mold - mnew); m_s[r] = mnew; }
        __syncthreads();

        if (g == 0)
            l_s[r] = l_s[r] * alpha_s[r]
                   + red_l[r] + red_l[64 + r] + red_l[128 + r] + red_l[192 + r];

        // Rescale O by alpha, then O += P @ V
        #pragma unroll
        for (int i = 0; i < 4; i++) {
            float a = alpha_s[tr * 4 + i];
            #pragma unroll
            for (int j = 0; j < 4; j++) o[i][j] *= a;
        }
        #pragma unroll 8
        for (int j = 0; j < 64; j++) {
            float4 pv = *(const float4*)&Pt[j * 64 + tr * 4];
            float4 vv = *(const float4*)&Vs[j * 64 + tc * 4];
            float pa[4] = {pv.x, pv.y, pv.z, pv.w};
            float va[4] = {vv.x, vv.y, vv.z, vv.w};
            #pragma unroll
            for (int i = 0; i < 4; i++)
                #pragma unroll
                for (int jj = 0; jj < 4; jj++) o[i][jj] += pa[i] * va[jj];
        }
    }
    __syncthreads();   // final l_s visible

    // Epilogue: y[b, m0+i, h*64+e] = o / l
    const int b = bh >> 4, h = bh & 15;
    #pragma unroll
    for (int i = 0; i < 4; i++) {
        int row = tr * 4 + i;
        float inv = 1.f / l_s[row];
        float4 w = make_float4(o[i][0] * inv, o[i][1] * inv,
                               o[i][2] * inv, o[i][3] * inv);
        *(float4*)&g_y[((size_t)(b * TT + m0 + row)) * CC + h * EE + tc * 4] = w;
    }
}

// ---------------------------------------------------------------------------
extern "C" void kernel_launch(void* const* d_in, const int* in_sizes, int n_in,
                              void* d_out, int out_size) {
    const float* x       = (const float*)d_in[0];
    const float* k_cache = (const float*)d_in[1];
    const float* v_cache = (const float*)d_in[2];
    const float* Wqkv    = (const float*)d_in[3];
    const float* bqkv    = (const float*)d_in[4];
    const float* Wproj   = (const float*)d_in[5];
    const float* bproj   = (const float*)d_in[6];
    float* out           = (float*)d_out;

    cudaFuncSetAttribute(attn_kernel,
                         cudaFuncAttributeMaxDynamicSharedMemorySize,
                         ATT_SMEM_BYTES);

    qkv_gemm_kernel<<<dim3(24, 32), 256>>>(x, Wqkv, bqkv);
    attn_kernel<<<dim3(8, 128), 256, ATT_SMEM_BYTES>>>(k_cache, v_cache);
    proj_gemm_kernel<<<dim3(8, 32), 256>>>(Wproj, bproj, out);
}

// round 4
// speedup vs baseline: 1.1547x; 1.1547x over previous
#include <cuda_runtime.h>
#include <cuda_bf16.h>
#include <cstdint>
#include <math.h>

#define BB 8
#define TT 512
#define CC 1024
#define HH 16
#define EE 64
#define LL 2048

// ---------------------------------------------------------------------------
// Scratch (__device__ globals; no allocation allowed)
// ---------------------------------------------------------------------------
__device__ float g_q[BB*HH*TT*EE];   // [B,H,T,E]
__device__ float g_k[BB*HH*TT*EE];
__device__ float g_v[BB*HH*TT*EE];
__device__ float g_y[BB*TT*CC];      // [B,T,C] attention output

__device__ __nv_bfloat16 g_xhi[BB*TT*CC];
__device__ __nv_bfloat16 g_xlo[BB*TT*CC];
__device__ __nv_bfloat16 g_yhi[BB*TT*CC];
__device__ __nv_bfloat16 g_ylo[BB*TT*CC];
__device__ __nv_bfloat16 g_wqkv_hi[3*CC*CC];   // [N=3072][K=1024] (transposed)
__device__ __nv_bfloat16 g_wqkv_lo[3*CC*CC];
__device__ __nv_bfloat16 g_wp_hi[CC*CC];       // [N=1024][K=1024]
__device__ __nv_bfloat16 g_wp_lo[CC*CC];

// ---------------------------------------------------------------------------
// mma.sync m16n8k16 bf16 (portable sm_80+ PTX; no tcgen05 — harness PTX
// stage targets plain sm_103 which rejects arch-specific instructions)
// ---------------------------------------------------------------------------
__device__ __forceinline__ void mma16816(float c[4],
    uint32_t a0, uint32_t a1, uint32_t a2, uint32_t a3,
    uint32_t b0, uint32_t b1)
{
    asm volatile(
        "mma.sync.aligned.m16n8k16.row.col.f32.bf16.bf16.f32 "
        "{%0,%1,%2,%3}, {%4,%5,%6,%7}, {%8,%9}, {%0,%1,%2,%3};"
        : "+f"(c[0]), "+f"(c[1]), "+f"(c[2]), "+f"(c[3])
        : "r"(a0), "r"(a1), "r"(a2), "r"(a3), "r"(b0), "r"(b1));
}

// ---------------------------------------------------------------------------
// bf16x3 mma.sync GEMM core.
// C[128,128] = (Ahi+Alo)[128,1024] * (Bhi+Blo)^T  (B stored [N][K])
// 256 threads = 8 warps (2 m x 4 n), warp tile 64x32, KC=32 chunks.
// smem planes pitch 40 halfwords (bank-conflict-free fragment loads).
// Accumulators c[4][4][4] (m-tiles x n-tiles x frag).
// ---------------------------------------------------------------------------
#define PITCH 40
#define PLANE (128 * PITCH)

struct GemmSmem { __nv_bfloat16 s[4 * PLANE]; };   // 40 KB (static ok)

__device__ __forceinline__ void tc_gemm_mma(
    const __nv_bfloat16* __restrict__ Ahi, const __nv_bfloat16* __restrict__ Alo,
    const __nv_bfloat16* __restrict__ Bhi, const __nv_bfloat16* __restrict__ Blo,
    int m0, int n0, __nv_bfloat16* S, float c[4][4][4])
{
    const int tid = threadIdx.x;
    const int wid = tid >> 5, lane = tid & 31;
    const int wm = wid & 1, wn = wid >> 1;       // warp -> (m 0..1, n 0..3)
    const int qr = lane >> 2, qc = lane & 3;

    #pragma unroll
    for (int i = 0; i < 4; i++)
        #pragma unroll
        for (int j = 0; j < 4; j++)
            #pragma unroll
            for (int t = 0; t < 4; t++) c[i][j][t] = 0.f;

    __nv_bfloat16* sAh = S;
    __nv_bfloat16* sAl = S + PLANE;
    __nv_bfloat16* sBh = S + 2 * PLANE;
    __nv_bfloat16* sBl = S + 3 * PLANE;

    const int r = tid >> 1, hh = (tid & 1) * 16;  // loader: row, 16-col half

    for (int kc = 0; kc < 32; kc++) {
        const int k0 = kc * 32;
        // gmem -> regs
        uint4 va0 = *(const uint4*)(Ahi + (size_t)(m0 + r) * 1024 + k0 + hh);
        uint4 va1 = *(const uint4*)(Ahi + (size_t)(m0 + r) * 1024 + k0 + hh + 8);
        uint4 vb0 = *(const uint4*)(Alo + (size_t)(m0 + r) * 1024 + k0 + hh);
        uint4 vb1 = *(const uint4*)(Alo + (size_t)(m0 + r) * 1024 + k0 + hh + 8);
        uint4 vc0 = *(const uint4*)(Bhi + (size_t)(n0 + r) * 1024 + k0 + hh);
        uint4 vc1 = *(const uint4*)(Bhi + (size_t)(n0 + r) * 1024 + k0 + hh + 8);
        uint4 vd0 = *(const uint4*)(Blo + (size_t)(n0 + r) * 1024 + k0 + hh);
        uint4 vd1 = *(const uint4*)(Blo + (size_t)(n0 + r) * 1024 + k0 + hh + 8);
        __syncthreads();
        *(uint4*)(sAh + r * PITCH + hh)     = va0;
        *(uint4*)(sAh + r * PITCH + hh + 8) = va1;
        *(uint4*)(sAl + r * PITCH + hh)     = vb0;
        *(uint4*)(sAl + r * PITCH + hh + 8) = vb1;
        *(uint4*)(sBh + r * PITCH + hh)     = vc0;
        *(uint4*)(sBh + r * PITCH + hh + 8) = vc1;
        *(uint4*)(sBl + r * PITCH + hh)     = vd0;
        *(uint4*)(sBl + r * PITCH + hh + 8) = vd1;
        __syncthreads();

        // 3 passes: hi*hi, hi*lo, lo*hi
        #pragma unroll
        for (int p = 0; p < 3; p++) {
            const __nv_bfloat16* At = (p == 2) ? sAl : sAh;
            const __nv_bfloat16* Bt = (p == 1) ? sBl : sBh;
            #pragma unroll
            for (int k16 = 0; k16 < 2; k16++) {
                const int kk = k16 * 16 + qc * 2;
                uint32_t a[4][4];
                #pragma unroll
                for (int i = 0; i < 4; i++) {
                    const __nv_bfloat16* ab = At + (wm * 64 + i * 16 + qr) * PITCH + kk;
                    a[i][0] = *(const uint32_t*)ab;
                    a[i][1] = *(const uint32_t*)(ab + 8 * PITCH);
                    a[i][2] = *(const uint32_t*)(ab + 8);
                    a[i][3] = *(const uint32_t*)(ab + 8 * PITCH + 8);
                }
                uint32_t b[4][2];
                #pragma unroll
                for (int j = 0; j < 4; j++) {
                    const __nv_bfloat16* bb = Bt + (wn * 32 + j * 8 + qr) * PITCH + kk;
                    b[j][0] = *(const uint32_t*)bb;
                    b[j][1] = *(const uint32_t*)(bb + 8);
                }
                #pragma unroll
                for (int i = 0; i < 4; i++)
                    #pragma unroll
                    for (int j = 0; j < 4; j++)
                        mma16816(c[i][j], a[i][0], a[i][1], a[i][2], a[i][3],
                                 b[j][0], b[j][1]);
            }
        }
    }
}

// ---------------------------------------------------------------------------
// QKV GEMM: grid (24, 32); epilogue splits into g_q/g_k/g_v head layout
// ---------------------------------------------------------------------------
__global__ __launch_bounds__(256) void qkv_mma_kernel(const float* __restrict__ bias)
{
    __shared__ GemmSmem sm;
    const int m0 = blockIdx.y * 128, n0 = blockIdx.x * 128;
    float c[4][4][4];
    tc_gemm_mma(g_xhi, g_xlo, g_wqkv_hi, g_wqkv_lo, m0, n0, sm.s, c);

    const int tid = threadIdx.x, wid = tid >> 5, lane = tid & 31;
    const int wm = wid & 1, wn = wid >> 1;
    const int qr = lane >> 2, qc = lane & 3;

    #pragma unroll
    for (int i = 0; i < 4; i++) {
        #pragma unroll
        for (int j = 0; j < 4; j++) {
            const int n = n0 + wn * 32 + j * 8 + qc * 2;
            const int part = n >> 10;
            const int h = (n & 1023) >> 6;
            const int e = n & 63;
            float* dst = (part == 0) ? g_q : (part == 1) ? g_k : g_v;
            const float b0 = bias[n], b1 = bias[n + 1];
            #pragma unroll
            for (int half = 0; half < 2; half++) {
                const int m = m0 + wm * 64 + i * 16 + qr + half * 8;
                const int bb = m >> 9, t = m & 511;
                float2 w = make_float2(c[i][j][half * 2] + b0,
                                       c[i][j][half * 2 + 1] + b1);
                *(float2*)&dst[(((size_t)(bb * HH + h) * TT + t) << 6) + e] = w;
            }
        }
    }
}

// ---------------------------------------------------------------------------
// Proj GEMM: grid (8, 32)
// ---------------------------------------------------------------------------
__global__ __launch_bounds__(256) void proj_mma_kernel(const float* __restrict__ bias,
                                                       float* __restrict__ out)
{
    __shared__ GemmSmem sm;
    const int m0 = blockIdx.y * 128, n0 = blockIdx.x * 128;
    float c[4][4][4];
    tc_gemm_mma(g_yhi, g_ylo, g_wp_hi, g_wp_lo, m0, n0, sm.s, c);

    const int tid = threadIdx.x, wid = tid >> 5, lane = tid & 31;
    const int wm = wid & 1, wn = wid >> 1;
    const int qr = lane >> 2, qc = lane & 3;

    #pragma unroll
    for (int i = 0; i < 4; i++) {
        #pragma unroll
        for (int j = 0; j < 4; j++) {
            const int n = n0 + wn * 32 + j * 8 + qc * 2;
            const float b0 = bias[n], b1 = bias[n + 1];
            #pragma unroll
            for (int half = 0; half < 2; half++) {
                const int m = m0 + wm * 64 + i * 16 + qr + half * 8;
                float2 w = make_float2(c[i][j][half * 2] + b0,
                                       c[i][j][half * 2 + 1] + b1);
                *(float2*)&out[(size_t)m * 1024 + n] = w;
            }
        }
    }
}

// ---------------------------------------------------------------------------
// Elementwise split fp32 -> (bf16 hi, bf16 lo). n4 = n/4.
// ---------------------------------------------------------------------------
__global__ __launch_bounds__(256) void split_kernel(const float* __restrict__ in,
                                                    __nv_bfloat16* __restrict__ hi,
                                                    __nv_bfloat16* __restrict__ lo,
                                                    int n4)
{
    int i = blockIdx.x * 256 + threadIdx.x;
    if (i >= n4) return;
    float4 v = ((const float4*)in)[i];
    __nv_bfloat16 h[4], l[4];
    float a[4] = {v.x, v.y, v.z, v.w};
    #pragma unroll
    for (int j = 0; j < 4; j++) {
        h[j] = __float2bfloat16_rn(a[j]);
        l[j] = __float2bfloat16_rn(a[j] - __bfloat162float(h[j]));
    }
    ((uint2*)hi)[i] = *(uint2*)h;
    ((uint2*)lo)[i] = *(uint2*)l;
}

// ---------------------------------------------------------------------------
// Transpose + split: W[K][N] fp32 -> out[N][K] bf16 hi/lo. block (32,8)
// ---------------------------------------------------------------------------
__global__ __launch_bounds__(256) void tsplit_kernel(const float* __restrict__ W,
                                                     __nv_bfloat16* __restrict__ hi,
                                                     __nv_bfloat16* __restrict__ lo,
                                                     int K, int N)
{
    __shared__ float tile[32][33];
    const int nx = blockIdx.x * 32, kx = blockIdx.y * 32;
    const int tx = threadIdx.x, ty = threadIdx.y;
    #pragma unroll
    for (int r = ty; r < 32; r += 8)
        tile[r][tx] = W[(size_t)(kx + r) * N + nx + tx];
    __syncthreads();
    #pragma unroll
    for (int r = ty; r < 32; r += 8) {
        float x = tile[tx][r];   // = W[kx+tx][nx+r]
        __nv_bfloat16 h = __float2bfloat16_rn(x);
        __nv_bfloat16 l = __float2bfloat16_rn(x - __bfloat162float(h));
        size_t o = (size_t)(nx + r) * K + kx + tx;
        hi[o] = h;
        lo[o] = l;
    }
}

// ---------------------------------------------------------------------------
// Flash attention (identical to the R1 passing version)
// ---------------------------------------------------------------------------
#define ATT_SMEM_FLOATS (4096*4 + 64*65 + 256*2 + 64*3)
#define ATT_SMEM_BYTES  (ATT_SMEM_FLOATS * 4)

__global__ __launch_bounds__(256) void attn_kernel(
    const float* __restrict__ k_cache, const float* __restrict__ v_cache)
{
    extern __shared__ float sm[];
    float* Qt      = sm;
    float* Kt      = Qt + 4096;
    float* Vs      = Kt + 4096;
    float* Ss      = Vs + 4096;
    float* Pt      = Ss + 64 * 65;
    float* red_m   = Pt + 4096;
    float* red_l   = red_m + 256;
    float* m_s     = red_l + 256;
    float* l_s     = m_s + 64;
    float* alpha_s = l_s + 64;

    const int tid = threadIdx.x;
    const int bh  = blockIdx.y;
    const int m0  = blockIdx.x * 64;
    const int tc  = tid & 15, tr = tid >> 4;

    const float* qptr = g_q + (bh * TT + m0) * EE;
    const float* knew = g_k + bh * TT * EE;
    const float* vnew = g_v + bh * TT * EE;
    const float* kc   = k_cache + (size_t)bh * LL * EE;
    const float* vc   = v_cache + (size_t)bh * LL * EE;

    #pragma unroll
    for (int ii = 0; ii < 4; ii++) {
        int f = ii * 256 + tid;
        int r = f >> 4, e0 = (f & 15) << 2;
        float4 v = *(const float4*)&qptr[r * EE + e0];
        Qt[(e0 + 0) * 64 + r] = v.x * 0.125f;
        Qt[(e0 + 1) * 64 + r] = v.y * 0.125f;
        Qt[(e0 + 2) * 64 + r] = v.z * 0.125f;
        Qt[(e0 + 3) * 64 + r] = v.w * 0.125f;
    }
    if (tid < 64) { m_s[tid] = -1e30f; l_s[tid] = 0.f; }

    float o[4][4];
    #pragma unroll
    for (int i = 0; i < 4; i++)
        #pragma unroll
        for (int j = 0; j < 4; j++) o[i][j] = 0.f;

    const int n_tiles = 32 + (m0 >> 6) + 1;

    for (int kt = 0; kt < n_tiles; kt++) {
        const float *ksrc, *vsrc;
        if (kt < 32) { ksrc = kc + kt * 64 * EE;           vsrc = vc + kt * 64 * EE; }
        else         { ksrc = knew + (kt - 32) * 64 * EE;  vsrc = vnew + (kt - 32) * 64 * EE; }

        float4 kreg[4], vreg[4];
        #pragma unroll
        for (int ii = 0; ii < 4; ii++) {
            int f = ii * 256 + tid;
            int r = f >> 4, e0 = (f & 15) << 2;
            kreg[ii] = *(const float4*)&ksrc[r * EE + e0];
            vreg[ii] = *(const float4*)&vsrc[r * EE + e0];
        }
        __syncthreads();
        #pragma unroll
        for (int ii = 0; ii < 4; ii++) {
            int f = ii * 256 + tid;
            int r = f >> 4, e0 = (f & 15) << 2;
            Kt[(e0 + 0) * 64 + r] = kreg[ii].x;
            Kt[(e0 + 1) * 64 + r] = kreg[ii].y;
            Kt[(e0 + 2) * 64 + r] = kreg[ii].z;
            Kt[(e0 + 3) * 64 + r] = kreg[ii].w;
            *(float4*)&Vs[r * 64 + e0] = vreg[ii];
        }
        __syncthreads();

        float s[4][4];
        #pragma unroll
        for (int i = 0; i < 4; i++)
            #pragma unroll
            for (int j = 0; j < 4; j++) s[i][j] = 0.f;
        #pragma unroll 8
        for (int e = 0; e < 64; e++) {
            float4 qv = *(const float4*)&Qt[e * 64 + tr * 4];
            float4 kv = *(const float4*)&Kt[e * 64 + tc * 4];
            float qa[4] = {qv.x, qv.y, qv.z, qv.w};
            float ka[4] = {kv.x, kv.y, kv.z, kv.w};
            #pragma unroll
            for (int i = 0; i < 4; i++)
                #pragma unroll
                for (int j = 0; j < 4; j++) s[i][j] += qa[i] * ka[j];
        }

        const bool diag = (kt == n_tiles - 1);
        #pragma unroll
        for (int i = 0; i < 4; i++)
            #pragma unroll
            for (int j = 0; j < 4; j++) {
                float v = s[i][j];
                if (diag && (tc * 4 + j) > (tr * 4 + i)) v = -1e30f;
                Ss[(tr * 4 + i) * 65 + tc * 4 + j] = v;
            }
        __syncthreads();

        const int rr = tid & 63, g = tid >> 6;
        const float* srow = &Ss[rr * 65 + g * 16];
        float mt = srow[0];
        #pragma unroll
        for (int jj = 1; jj < 16; jj++) mt = fmaxf(mt, srow[jj]);
        red_m[g * 64 + rr] = mt;
        __syncthreads();

        float mold = m_s[rr];
        float mnew = fmaxf(fmaxf(red_m[rr], red_m[64 + rr]),
                           fmaxf(red_m[128 + rr], red_m[192 + rr]));
        mnew = fmaxf(mnew, mold);
        float lsum = 0.f;
        #pragma unroll
        for (int jj = 0; jj < 16; jj++) {
            float p = __expf(srow[jj] - mnew);
            Pt[(g * 16 + jj) * 64 + rr] = p;
            lsum += p;
        }
        red_l[g * 64 + rr] = lsum;
        if (g == 0) { alpha_s[rr] = __expf(mold - mnew); m_s[rr] = mnew; }
        __syncthreads();

        if (g == 0)
            l_s[rr] = l_s[rr] * alpha_s[rr]
                    + red_l[rr] + red_l[64 + rr] + red_l[128 + rr] + red_l[192 + rr];

        #pragma unroll
        for (int i = 0; i < 4; i++) {
            float a = alpha_s[tr * 4 + i];
            #pragma unroll
            for (int j = 0; j < 4; j++) o[i][j] *= a;
        }
        #pragma unroll 8
        for (int j = 0; j < 64; j++) {
            float4 pv = *(const float4*)&Pt[j * 64 + tr * 4];
            float4 vv = *(const float4*)&Vs[j * 64 + tc * 4];
            float pa[4] = {pv.x, pv.y, pv.z, pv.w};
            float va[4] = {vv.x, vv.y, vv.z, vv.w};
            #pragma unroll
            for (int i = 0; i < 4; i++)
                #pragma unroll
                for (int jj = 0; jj < 4; jj++) o[i][jj] += pa[i] * va[jj];
        }
    }
    __syncthreads();

    const int b = bh >> 4, h = bh & 15;
    #pragma unroll
    for (int i = 0; i < 4; i++) {
        int row = tr * 4 + i;
        float inv = 1.f / l_s[row];
        float4 w = make_float4(o[i][0] * inv, o[i][1] * inv,
                               o[i][2] * inv, o[i][3] * inv);
        *(float4*)&g_y[((size_t)(b * TT + m0 + row)) * CC + h * EE + tc * 4] = w;
    }
}

// ---------------------------------------------------------------------------
extern "C" void kernel_launch(void* const* d_in, const int* in_sizes, int n_in,
                              void* d_out, int out_size) {
    const float* x       = (const float*)d_in[0];
    const float* k_cache = (const float*)d_in[1];
    const float* v_cache = (const float*)d_in[2];
    const float* Wqkv    = (const float*)d_in[3];
    const float* bqkv    = (const float*)d_in[4];
    const float* Wproj   = (const float*)d_in[5];
    const float* bproj   = (const float*)d_in[6];
    float* out           = (float*)d_out;

    cudaFuncSetAttribute(attn_kernel, cudaFuncAttributeMaxDynamicSharedMemorySize,
                         ATT_SMEM_BYTES);

    __nv_bfloat16 *xhi, *xlo, *yhi, *ylo, *wqh, *wql, *wph, *wpl;
    cudaGetSymbolAddress((void**)&xhi, g_xhi);
    cudaGetSymbolAddress((void**)&xlo, g_xlo);
    cudaGetSymbolAddress((void**)&yhi, g_yhi);
    cudaGetSymbolAddress((void**)&ylo, g_ylo);
    cudaGetSymbolAddress((void**)&wqh, g_wqkv_hi);
    cudaGetSymbolAddress((void**)&wql, g_wqkv_lo);
    cudaGetSymbolAddress((void**)&wph, g_wp_hi);
    cudaGetSymbolAddress((void**)&wpl, g_wp_lo);
    float* ybuf;
    cudaGetSymbolAddress((void**)&ybuf, g_y);

    // Prep: split x, transpose+split weights  (n4 = 1,048,576 -> 4096 blocks)
    split_kernel<<<4096, 256>>>(x, xhi, xlo, BB*TT*CC/4);
    tsplit_kernel<<<dim3(96, 32), dim3(32, 8)>>>(Wqkv, wqh, wql, 1024, 3072);
    tsplit_kernel<<<dim3(32, 32), dim3(32, 8)>>>(Wproj, wph, wpl, 1024, 1024);

    // QKV GEMM (tensor core via mma.sync) -> g_q/g_k/g_v
    qkv_mma_kernel<<<dim3(24, 32), 256>>>(bqkv);

    // Attention -> g_y
    attn_kernel<<<dim3(8, 128), 256, ATT_SMEM_BYTES>>>(k_cache, v_cache);

    // Split y, proj GEMM -> out
    split_kernel<<<4096, 256>>>(ybuf, yhi, ylo, BB*TT*CC/4);
    proj_mma_kernel<<<dim3(8, 32), 256>>>(bproj, out);
}

// round 6
// speedup vs baseline: 2.3231x; 2.0118x over previous
#include <cuda_runtime.h>
#include <cuda_bf16.h>
#include <cstdint>
#include <math.h>

#define BB 8
#define TT 512
#define CC 1024
#define HH 16
#define EE 64
#define LL 2048
#define SQ 2560                     // L + T
#define QSCALE 0.1803368801111244f  // 0.125 * log2(e)

// ---------------------------------------------------------------------------
// Scratch (__device__ globals; no allocation allowed)
// ---------------------------------------------------------------------------
__device__ __nv_bfloat16 g_xhi[BB*TT*CC];
__device__ __nv_bfloat16 g_xlo[BB*TT*CC];
__device__ __nv_bfloat16 g_yhi[BB*TT*CC];
__device__ __nv_bfloat16 g_ylo[BB*TT*CC];
__device__ __nv_bfloat16 g_wqkv_hi[3*CC*CC];   // [N=3072][K=1024]
__device__ __nv_bfloat16 g_wqkv_lo[3*CC*CC];
__device__ __nv_bfloat16 g_wp_hi[CC*CC];       // [N=1024][K=1024]
__device__ __nv_bfloat16 g_wp_lo[CC*CC];

__device__ __nv_bfloat16 g_qhi[BB*HH*TT*EE];   // [bh][t][e], pre-scaled
__device__ __nv_bfloat16 g_qlo[BB*HH*TT*EE];
__device__ __nv_bfloat16 g_khi[BB*HH*SQ*EE];   // [bh][s][e], s=0..2559
__device__ __nv_bfloat16 g_klo[BB*HH*SQ*EE];
__device__ __nv_bfloat16 g_vthi[BB*HH*EE*SQ];  // [bh][e][s] (transposed)
__device__ __nv_bfloat16 g_vtlo[BB*HH*EE*SQ];

// ---------------------------------------------------------------------------
// Helpers
// ---------------------------------------------------------------------------
__device__ __forceinline__ void mma16816(float c[4],
    uint32_t a0, uint32_t a1, uint32_t a2, uint32_t a3,
    uint32_t b0, uint32_t b1)
{
    asm volatile(
        "mma.sync.aligned.m16n8k16.row.col.f32.bf16.bf16.f32 "
        "{%0,%1,%2,%3}, {%4,%5,%6,%7}, {%8,%9}, {%0,%1,%2,%3};"
        : "+f"(c[0]), "+f"(c[1]), "+f"(c[2]), "+f"(c[3])
        : "r"(a0), "r"(a1), "r"(a2), "r"(a3), "r"(b0), "r"(b1));
}
__device__ __forceinline__ float ex2(float x) {
    float r; asm("ex2.approx.ftz.f32 %0, %1;" : "=f"(r) : "f"(x)); return r;
}
__device__ __forceinline__ uint32_t pack_hi(float a, float b, float& ra, float& rb) {
    __nv_bfloat162 h = __floats2bfloat162_rn(a, b);
    ra = a - __low2float(h); rb = b - __high2float(h);
    return *(uint32_t*)&h;
}
__device__ __forceinline__ uint32_t pack_bf(float a, float b) {
    __nv_bfloat162 h = __floats2bfloat162_rn(a, b);
    return *(uint32_t*)&h;
}

// ---------------------------------------------------------------------------
// bf16x3 mma.sync GEMM core (measured 205 TF/s effective)
// ---------------------------------------------------------------------------
#define PITCH 40
#define PLANE (128 * PITCH)
struct GemmSmem { __nv_bfloat16 s[4 * PLANE]; };   // 40 KB

__device__ __forceinline__ void tc_gemm_mma(
    const __nv_bfloat16* __restrict__ Ahi, const __nv_bfloat16* __restrict__ Alo,
    const __nv_bfloat16* __restrict__ Bhi, const __nv_bfloat16* __restrict__ Blo,
    int m0, int n0, __nv_bfloat16* S, float c[4][4][4])
{
    const int tid = threadIdx.x;
    const int wid = tid >> 5, lane = tid & 31;
    const int wm = wid & 1, wn = wid >> 1;
    const int qr = lane >> 2, qc = lane & 3;

    #pragma unroll
    for (int i = 0; i < 4; i++)
        #pragma unroll
        for (int j = 0; j < 4; j++)
            #pragma unroll
            for (int t = 0; t < 4; t++) c[i][j][t] = 0.f;

    __nv_bfloat16* sAh = S;
    __nv_bfloat16* sAl = S + PLANE;
    __nv_bfloat16* sBh = S + 2 * PLANE;
    __nv_bfloat16* sBl = S + 3 * PLANE;

    const int r = tid >> 1, hh = (tid & 1) * 16;

    for (int kc = 0; kc < 32; kc++) {
        const int k0 = kc * 32;
        uint4 va0 = *(const uint4*)(Ahi + (size_t)(m0 + r) * 1024 + k0 + hh);
        uint4 va1 = *(const uint4*)(Ahi + (size_t)(m0 + r) * 1024 + k0 + hh + 8);
        uint4 vb0 = *(const uint4*)(Alo + (size_t)(m0 + r) * 1024 + k0 + hh);
        uint4 vb1 = *(const uint4*)(Alo + (size_t)(m0 + r) * 1024 + k0 + hh + 8);
        uint4 vc0 = *(const uint4*)(Bhi + (size_t)(n0 + r) * 1024 + k0 + hh);
        uint4 vc1 = *(const uint4*)(Bhi + (size_t)(n0 + r) * 1024 + k0 + hh + 8);
        uint4 vd0 = *(const uint4*)(Blo + (size_t)(n0 + r) * 1024 + k0 + hh);
        uint4 vd1 = *(const uint4*)(Blo + (size_t)(n0 + r) * 1024 + k0 + hh + 8);
        __syncthreads();
        *(uint4*)(sAh + r * PITCH + hh)     = va0;
        *(uint4*)(sAh + r * PITCH + hh + 8) = va1;
        *(uint4*)(sAl + r * PITCH + hh)     = vb0;
        *(uint4*)(sAl + r * PITCH + hh + 8) = vb1;
        *(uint4*)(sBh + r * PITCH + hh)     = vc0;
        *(uint4*)(sBh + r * PITCH + hh + 8) = vc1;
        *(uint4*)(sBl + r * PITCH + hh)     = vd0;
        *(uint4*)(sBl + r * PITCH + hh + 8) = vd1;
        __syncthreads();

        #pragma unroll
        for (int p = 0; p < 3; p++) {
            const __nv_bfloat16* At = (p == 2) ? sAl : sAh;
            const __nv_bfloat16* Bt = (p == 1) ? sBl : sBh;
            #pragma unroll
            for (int k16 = 0; k16 < 2; k16++) {
                const int kk = k16 * 16 + qc * 2;
                uint32_t a[4][4];
                #pragma unroll
                for (int i = 0; i < 4; i++) {
                    const __nv_bfloat16* ab = At + (wm * 64 + i * 16 + qr) * PITCH + kk;
                    a[i][0] = *(const uint32_t*)ab;
                    a[i][1] = *(const uint32_t*)(ab + 8 * PITCH);
                    a[i][2] = *(const uint32_t*)(ab + 8);
                    a[i][3] = *(const uint32_t*)(ab + 8 * PITCH + 8);
                }
                uint32_t b[4][2];
                #pragma unroll
                for (int j = 0; j < 4; j++) {
                    const __nv_bfloat16* bb = Bt + (wn * 32 + j * 8 + qr) * PITCH + kk;
                    b[j][0] = *(const uint32_t*)bb;
                    b[j][1] = *(const uint32_t*)(bb + 8);
                }
                #pragma unroll
                for (int i = 0; i < 4; i++)
                    #pragma unroll
                    for (int j = 0; j < 4; j++)
                        mma16816(c[i][j], a[i][0], a[i][1], a[i][2], a[i][3],
                                 b[j][0], b[j][1]);
            }
        }
    }
}

// ---------------------------------------------------------------------------
// QKV GEMM: epilogue writes pre-scaled bf16-split q, k (seq offset 2048),
// v transposed — exactly the layouts the attention kernel consumes.
// ---------------------------------------------------------------------------
__global__ __launch_bounds__(256) void qkv_mma_kernel(const float* __restrict__ bias)
{
    __shared__ GemmSmem sm;
    const int m0 = blockIdx.y * 128, n0 = blockIdx.x * 128;
    float c[4][4][4];
    tc_gemm_mma(g_xhi, g_xlo, g_wqkv_hi, g_wqkv_lo, m0, n0, sm.s, c);

    const int tid = threadIdx.x, wid = tid >> 5, lane = tid & 31;
    const int wm = wid & 1, wn = wid >> 1;
    const int qr = lane >> 2, qc = lane & 3;

    #pragma unroll
    for (int i = 0; i < 4; i++) {
        #pragma unroll
        for (int j = 0; j < 4; j++) {
            const int n = n0 + wn * 32 + j * 8 + qc * 2;
            const int part = n >> 10;
            const int h = (n & 1023) >> 6;
            const int e = n & 63;
            const float b0 = bias[n], b1 = bias[n + 1];
            #pragma unroll
            for (int half = 0; half < 2; half++) {
                const int m = m0 + wm * 64 + i * 16 + qr + half * 8;
                const int bb = m >> 9, t = m & 511;
                const int bh = bb * HH + h;
                float v0 = c[i][j][half * 2] + b0;
                float v1 = c[i][j][half * 2 + 1] + b1;
                if (part == 0) {
                    v0 *= QSCALE; v1 *= QSCALE;
                    float l0, l1;
                    uint32_t hi = pack_hi(v0, v1, l0, l1);
                    uint32_t lo = pack_bf(l0, l1);
                    size_t off = ((size_t)bh * TT + t) * 64 + e;
                    *(uint32_t*)(g_qhi + off) = hi;
                    *(uint32_t*)(g_qlo + off) = lo;
                } else if (part == 1) {
                    float l0, l1;
                    uint32_t hi = pack_hi(v0, v1, l0, l1);
                    uint32_t lo = pack_bf(l0, l1);
                    size_t off = ((size_t)bh * SQ + LL + t) * 64 + e;
                    *(uint32_t*)(g_khi + off) = hi;
                    *(uint32_t*)(g_klo + off) = lo;
                } else {
                    __nv_bfloat16 h0 = __float2bfloat16_rn(v0);
                    __nv_bfloat16 h1 = __float2bfloat16_rn(v1);
                    __nv_bfloat16 l0 = __float2bfloat16_rn(v0 - __bfloat162float(h0));
                    __nv_bfloat16 l1 = __float2bfloat16_rn(v1 - __bfloat162float(h1));
                    size_t o0 = ((size_t)bh * 64 + e) * SQ + LL + t;
                    size_t o1 = ((size_t)bh * 64 + e + 1) * SQ + LL + t;
                    g_vthi[o0] = h0; g_vtlo[o0] = l0;
                    g_vthi[o1] = h1; g_vtlo[o1] = l1;
                }
            }
        }
    }
}

// ---------------------------------------------------------------------------
// Proj GEMM: reads g_yhi/g_ylo written by attention
// ---------------------------------------------------------------------------
__global__ __launch_bounds__(256) void proj_mma_kernel(const float* __restrict__ bias,
                                                       float* __restrict__ out)
{
    __shared__ GemmSmem sm;
    const int m0 = blockIdx.y * 128, n0 = blockIdx.x * 128;
    float c[4][4][4];
    tc_gemm_mma(g_yhi, g_ylo, g_wp_hi, g_wp_lo, m0, n0, sm.s, c);

    const int tid = threadIdx.x, wid = tid >> 5, lane = tid & 31;
    const int wm = wid & 1, wn = wid >> 1;
    const int qr = lane >> 2, qc = lane & 3;

    #pragma unroll
    for (int i = 0; i < 4; i++) {
        #pragma unroll
        for (int j = 0; j < 4; j++) {
            const int n = n0 + wn * 32 + j * 8 + qc * 2;
            const float b0 = bias[n], b1 = bias[n + 1];
            #pragma unroll
            for (int half = 0; half < 2; half++) {
                const int m = m0 + wm * 64 + i * 16 + qr + half * 8;
                float2 w = make_float2(c[i][j][half * 2] + b0,
                                       c[i][j][half * 2 + 1] + b1);
                *(float2*)&out[(size_t)m * 1024 + n] = w;
            }
        }
    }
}

// ---------------------------------------------------------------------------
// Flash attention on mma.sync: 128 queries/CTA, 64-key tiles, bf16x3 QK & PV.
// Warp w owns rows 16w..16w+15; softmax fully in registers + 2 shfl.
// ---------------------------------------------------------------------------
__global__ __launch_bounds__(256) void attn_mma_kernel()
{
    __shared__ __nv_bfloat16 sKh[64*72], sKl[64*72], sVh[64*72], sVl[64*72];

    const int tid = threadIdx.x, wid = tid >> 5, lane = tid & 31;
    const int l4 = lane >> 2, qn = lane & 3;
    const int bh = blockIdx.y;
    const int qb = 3 - blockIdx.x;      // heavy blocks first
    const int base = qb * 128;

    // Persistent Q fragments (pre-scaled bf16 hi/lo)
    uint32_t aQh[4][4], aQl[4][4];
    {
        const __nv_bfloat16* qh = g_qhi + ((size_t)bh * TT + base + wid * 16) * 64;
        const __nv_bfloat16* ql = g_qlo + ((size_t)bh * TT + base + wid * 16) * 64;
        #pragma unroll
        for (int kk = 0; kk < 4; kk++) {
            const int c0 = kk * 16 + qn * 2;
            aQh[kk][0] = *(const uint32_t*)(qh + l4 * 64 + c0);
            aQh[kk][1] = *(const uint32_t*)(qh + (l4 + 8) * 64 + c0);
            aQh[kk][2] = *(const uint32_t*)(qh + l4 * 64 + c0 + 8);
            aQh[kk][3] = *(const uint32_t*)(qh + (l4 + 8) * 64 + c0 + 8);
            aQl[kk][0] = *(const uint32_t*)(ql + l4 * 64 + c0);
            aQl[kk][1] = *(const uint32_t*)(ql + (l4 + 8) * 64 + c0);
            aQl[kk][2] = *(const uint32_t*)(ql + l4 * 64 + c0 + 8);
            aQl[kk][3] = *(const uint32_t*)(ql + (l4 + 8) * 64 + c0 + 8);
        }
    }

    float O[8][4];
    #pragma unroll
    for (int j = 0; j < 8; j++)
        #pragma unroll
        for (int t = 0; t < 4; t++) O[j][t] = 0.f;
    float mrow[2] = {-1e30f, -1e30f};
    float lrow[2] = {0.f, 0.f};

    const __nv_bfloat16* Kh  = g_khi  + (size_t)bh * SQ * 64;
    const __nv_bfloat16* Kl  = g_klo  + (size_t)bh * SQ * 64;
    const __nv_bfloat16* Vth = g_vthi + (size_t)bh * 64 * SQ;
    const __nv_bfloat16* Vtl = g_vtlo + (size_t)bh * 64 * SQ;

    const int n_tiles = 32 + 2 * (qb + 1);

    for (int kt = 0; kt < n_tiles; kt++) {
        const int s0 = kt * 64;

        // Prefetch tile to regs, then stage to smem
        uint4 pkh[2], pkl[2], pvh[2], pvl[2];
        #pragma unroll
        for (int i = 0; i < 2; i++) {
            const int f = i * 256 + tid, r = f >> 3, cc = (f & 7) * 8;
            pkh[i] = *(const uint4*)(Kh  + (size_t)(s0 + r) * 64 + cc);
            pkl[i] = *(const uint4*)(Kl  + (size_t)(s0 + r) * 64 + cc);
            pvh[i] = *(const uint4*)(Vth + (size_t)r * SQ + s0 + cc);
            pvl[i] = *(const uint4*)(Vtl + (size_t)r * SQ + s0 + cc);
        }
        __syncthreads();
        #pragma unroll
        for (int i = 0; i < 2; i++) {
            const int f = i * 256 + tid, r = f >> 3, cc = (f & 7) * 8;
            *(uint4*)(sKh + r * 72 + cc) = pkh[i];
            *(uint4*)(sKl + r * 72 + cc) = pkl[i];
            *(uint4*)(sVh + r * 72 + cc) = pvh[i];
            *(uint4*)(sVl + r * 72 + cc) = pvl[i];
        }
        __syncthreads();

        // S = Q K^T  (3 bf16 passes)
        float S[8][4];
        #pragma unroll
        for (int j = 0; j < 8; j++)
            #pragma unroll
            for (int t = 0; t < 4; t++) S[j][t] = 0.f;

        #pragma unroll
        for (int kk = 0; kk < 4; kk++) {
            #pragma unroll
            for (int j = 0; j < 8; j++) {
                const __nv_bfloat16* kb = sKh + (j * 8 + l4) * 72 + kk * 16 + qn * 2;
                const __nv_bfloat16* kb2 = sKl + (j * 8 + l4) * 72 + kk * 16 + qn * 2;
                uint32_t bh0 = *(const uint32_t*)kb;
                uint32_t bh1 = *(const uint32_t*)(kb + 8);
                uint32_t bl0 = *(const uint32_t*)kb2;
                uint32_t bl1 = *(const uint32_t*)(kb2 + 8);
                mma16816(S[j], aQh[kk][0], aQh[kk][1], aQh[kk][2], aQh[kk][3], bh0, bh1);
                mma16816(S[j], aQh[kk][0], aQh[kk][1], aQh[kk][2], aQh[kk][3], bl0, bl1);
                mma16816(S[j], aQl[kk][0], aQl[kk][1], aQl[kk][2], aQl[kk][3], bh0, bh1);
            }
        }

        // Causal mask — row must be the BLOCK-local query row (incl. wid*16)
        if (kt >= n_tiles - 2) {
            const int lim = s0 - LL - base;
            #pragma unroll
            for (int j = 0; j < 8; j++)
                #pragma unroll
                for (int t = 0; t < 4; t++) {
                    const int col = j * 8 + qn * 2 + (t & 1);
                    const int row = wid * 16 + l4 + ((t >> 1) << 3);
                    if (col + lim > row) S[j][t] = -1e30f;
                }
        }

        // Online softmax (per row-half; 4-lane shfl reductions)
        #pragma unroll
        for (int h = 0; h < 2; h++) {
            float mt = -1e30f;
            #pragma unroll
            for (int j = 0; j < 8; j++)
                mt = fmaxf(mt, fmaxf(S[j][2 * h], S[j][2 * h + 1]));
            mt = fmaxf(mt, __shfl_xor_sync(0xffffffffu, mt, 1));
            mt = fmaxf(mt, __shfl_xor_sync(0xffffffffu, mt, 2));
            const float mn = fmaxf(mrow[h], mt);
            const float alpha = ex2(mrow[h] - mn);
            mrow[h] = mn;
            float ls = 0.f;
            #pragma unroll
            for (int j = 0; j < 8; j++) {
                float p0 = ex2(S[j][2 * h] - mn);
                float p1 = ex2(S[j][2 * h + 1] - mn);
                S[j][2 * h] = p0; S[j][2 * h + 1] = p1;
                ls += p0 + p1;
            }
            ls += __shfl_xor_sync(0xffffffffu, ls, 1);
            ls += __shfl_xor_sync(0xffffffffu, ls, 2);
            lrow[h] = lrow[h] * alpha + ls;
            #pragma unroll
            for (int j = 0; j < 8; j++) {
                O[j][2 * h] *= alpha; O[j][2 * h + 1] *= alpha;
            }
        }

        // Pack P -> A fragments (register-only; layouts match)
        uint32_t aPh[4][4], aPl[4][4];
        #pragma unroll
        for (int kk = 0; kk < 4; kk++) {
            const int j0 = 2 * kk, j1 = 2 * kk + 1;
            float l0, l1;
            aPh[kk][0] = pack_hi(S[j0][0], S[j0][1], l0, l1);
            aPl[kk][0] = pack_bf(l0, l1);
            aPh[kk][1] = pack_hi(S[j0][2], S[j0][3], l0, l1);
            aPl[kk][1] = pack_bf(l0, l1);
            aPh[kk][2] = pack_hi(S[j1][0], S[j1][1], l0, l1);
            aPl[kk][2] = pack_bf(l0, l1);
            aPh[kk][3] = pack_hi(S[j1][2], S[j1][3], l0, l1);
            aPl[kk][3] = pack_bf(l0, l1);
        }

        // O += P V  (3 bf16 passes; V^T in smem as B operand)
        #pragma unroll
        for (int kk = 0; kk < 4; kk++) {
            #pragma unroll
            for (int j = 0; j < 8; j++) {
                const __nv_bfloat16* vb = sVh + (j * 8 + l4) * 72 + kk * 16 + qn * 2;
                const __nv_bfloat16* vb2 = sVl + (j * 8 + l4) * 72 + kk * 16 + qn * 2;
                uint32_t bh0 = *(const uint32_t*)vb;
                uint32_t bh1 = *(const uint32_t*)(vb + 8);
                uint32_t bl0 = *(const uint32_t*)vb2;
                uint32_t bl1 = *(const uint32_t*)(vb2 + 8);
                mma16816(O[j], aPh[kk][0], aPh[kk][1], aPh[kk][2], aPh[kk][3], bh0, bh1);
                mma16816(O[j], aPh[kk][0], aPh[kk][1], aPh[kk][2], aPh[kk][3], bl0, bl1);
                mma16816(O[j], aPl[kk][0], aPl[kk][1], aPl[kk][2], aPl[kk][3], bh0, bh1);
            }
        }
    }

    // Epilogue: y = O / l, bf16-split directly into proj's input format
    const int b = bh >> 4, hh = bh & 15;
    #pragma unroll
    for (int h = 0; h < 2; h++) {
        const int t = base + wid * 16 + l4 + h * 8;
        const float inv = 1.f / lrow[h];
        #pragma unroll
        for (int j = 0; j < 8; j++) {
            const float y0 = O[j][2 * h] * inv;
            const float y1 = O[j][2 * h + 1] * inv;
            float l0, l1;
            uint32_t hi = pack_hi(y0, y1, l0, l1);
            uint32_t lo = pack_bf(l0, l1);
            const size_t off = ((size_t)(b * TT + t)) * CC + hh * 64 + j * 8 + qn * 2;
            *(uint32_t*)(g_yhi + off) = hi;
            *(uint32_t*)(g_ylo + off) = lo;
        }
    }
}

// ---------------------------------------------------------------------------
// Prep kernels
// ---------------------------------------------------------------------------
__global__ __launch_bounds__(256) void split_kernel(const float* __restrict__ in,
                                                    __nv_bfloat16* __restrict__ hi,
                                                    __nv_bfloat16* __restrict__ lo,
                                                    int n4)
{
    int i = blockIdx.x * 256 + threadIdx.x;
    if (i >= n4) return;
    float4 v = ((const float4*)in)[i];
    __nv_bfloat16 h[4], l[4];
    float a[4] = {v.x, v.y, v.z, v.w};
    #pragma unroll
    for (int j = 0; j < 4; j++) {
        h[j] = __float2bfloat16_rn(a[j]);
        l[j] = __float2bfloat16_rn(a[j] - __bfloat162float(h[j]));
    }
    ((uint2*)hi)[i] = *(uint2*)h;
    ((uint2*)lo)[i] = *(uint2*)l;
}

__global__ __launch_bounds__(256) void tsplit_kernel(const float* __restrict__ W,
                                                     __nv_bfloat16* __restrict__ hi,
                                                     __nv_bfloat16* __restrict__ lo,
                                                     int K, int N)
{
    __shared__ float tile[32][33];
    const int nx = blockIdx.x * 32, kx = blockIdx.y * 32;
    const int tx = threadIdx.x, ty = threadIdx.y;
    #pragma unroll
    for (int r = ty; r < 32; r += 8)
        tile[r][tx] = W[(size_t)(kx + r) * N + nx + tx];
    __syncthreads();
    #pragma unroll
    for (int r = ty; r < 32; r += 8) {
        float x = tile[tx][r];
        __nv_bfloat16 h = __float2bfloat16_rn(x);
        __nv_bfloat16 l = __float2bfloat16_rn(x - __bfloat162float(h));
        size_t o = (size_t)(nx + r) * K + kx + tx;
        hi[o] = h;
        lo[o] = l;
    }
}

// K cache: fp32 [bh][2048][64] -> bf16 hi/lo at [bh][s][e] (s < 2048)
__global__ __launch_bounds__(256) void kcache_prep(const float* __restrict__ kc)
{
    const size_t i = (size_t)blockIdx.x * 256 + threadIdx.x;   // < 4194304
    float4 v = ((const float4*)kc)[i];
    const size_t flat = i * 4;
    const size_t bh = flat >> 17;            // / (2048*64)
    const size_t rem = flat & 131071;
    const size_t s = rem >> 6, e = rem & 63;
    __nv_bfloat16 h[4], l[4];
    float a[4] = {v.x, v.y, v.z, v.w};
    #pragma unroll
    for (int j = 0; j < 4; j++) {
        h[j] = __float2bfloat16_rn(a[j]);
        l[j] = __float2bfloat16_rn(a[j] - __bfloat162float(h[j]));
    }
    const size_t off = (bh * SQ + s) * 64 + e;
    *(uint2*)(g_khi + off) = *(uint2*)h;
    *(uint2*)(g_klo + off) = *(uint2*)l;
}

// V cache: fp32 [bh][2048][64] -> transposed bf16 hi/lo [bh][e][s]
__global__ void vcache_prep(const float* __restrict__ vc)
{
    __shared__ float tile[32][33];
    const int bh = blockIdx.z;
    const int s0 = blockIdx.x * 32, e0 = blockIdx.y * 32;
    const int tx = threadIdx.x, ty = threadIdx.y;
    #pragma unroll
    for (int r = ty; r < 32; r += 8)
        tile[r][tx] = vc[((size_t)bh * LL + s0 + r) * 64 + e0 + tx];
    __syncthreads();
    #pragma unroll
    for (int r = ty; r < 32; r += 8) {
        float x = tile[tx][r];   // = vc[bh][s0+tx][e0+r]
        __nv_bfloat16 h = __float2bfloat16_rn(x);
        __nv_bfloat16 l = __float2bfloat16_rn(x - __bfloat162float(h));
        const size_t off = ((size_t)bh * 64 + e0 + r) * SQ + s0 + tx;
        g_vthi[off] = h;
        g_vtlo[off] = l;
    }
}

// ---------------------------------------------------------------------------
extern "C" void kernel_launch(void* const* d_in, const int* in_sizes, int n_in,
                              void* d_out, int out_size) {
    const float* x       = (const float*)d_in[0];
    const float* k_cache = (const float*)d_in[1];
    const float* v_cache = (const float*)d_in[2];
    const float* Wqkv    = (const float*)d_in[3];
    const float* bqkv    = (const float*)d_in[4];
    const float* Wproj   = (const float*)d_in[5];
    const float* bproj   = (const float*)d_in[6];
    float* out           = (float*)d_out;

    __nv_bfloat16 *xhi, *xlo, *wqh, *wql, *wph, *wpl;
    cudaGetSymbolAddress((void**)&xhi, g_xhi);
    cudaGetSymbolAddress((void**)&xlo, g_xlo);
    cudaGetSymbolAddress((void**)&wqh, g_wqkv_hi);
    cudaGetSymbolAddress((void**)&wql, g_wqkv_lo);
    cudaGetSymbolAddress((void**)&wph, g_wp_hi);
    cudaGetSymbolAddress((void**)&wpl, g_wp_lo);

    // Prep: input/weight splits + KV-cache conversion
    split_kernel<<<4096, 256>>>(x, xhi, xlo, BB*TT*CC/4);
    tsplit_kernel<<<dim3(96, 32), dim3(32, 8)>>>(Wqkv, wqh, wql, 1024, 3072);
    tsplit_kernel<<<dim3(32, 32), dim3(32, 8)>>>(Wproj, wph, wpl, 1024, 1024);
    kcache_prep<<<16384, 256>>>(k_cache);
    vcache_prep<<<dim3(64, 2, 128), dim3(32, 8)>>>(v_cache);

    // QKV GEMM -> bf16-split q/k/v in attention layouts
    qkv_mma_kernel<<<dim3(24, 32), 256>>>(bqkv);

    // Flash attention (tensor core) -> g_yhi/g_ylo
    attn_mma_kernel<<<dim3(4, 128), 256>>>();

    // Output projection
    proj_mma_kernel<<<dim3(8, 32), 256>>>(bproj, out);
}

// round 7
// speedup vs baseline: 2.9817x; 1.2835x over previous
#include <cuda_runtime.h>
#include <cuda_bf16.h>
#include <cstdint>
#include <math.h>

#define BB 8
#define TT 512
#define CC 1024
#define HH 16
#define EE 64
#define LL 2048
#define SQ 2560                     // L + T
#define QSCALE 0.1803368801111244f  // 0.125 * log2(e)

// ---------------------------------------------------------------------------
// Scratch (__device__ globals; no allocation allowed)
// ---------------------------------------------------------------------------
__device__ __nv_bfloat16 g_xhi[BB*TT*CC];
__device__ __nv_bfloat16 g_xlo[BB*TT*CC];
__device__ __nv_bfloat16 g_yhi[BB*TT*CC];
__device__ __nv_bfloat16 g_ylo[BB*TT*CC];
__device__ __nv_bfloat16 g_wqkv_hi[3*CC*CC];   // [N=3072][K=1024]
__device__ __nv_bfloat16 g_wqkv_lo[3*CC*CC];
__device__ __nv_bfloat16 g_wp_hi[CC*CC];       // [N=1024][K=1024]
__device__ __nv_bfloat16 g_wp_lo[CC*CC];

__device__ __nv_bfloat16 g_qhi[BB*HH*TT*EE];   // [bh][t][e], pre-scaled
__device__ __nv_bfloat16 g_qlo[BB*HH*TT*EE];
__device__ __nv_bfloat16 g_khi[BB*HH*SQ*EE];   // [bh][s][e]
__device__ __nv_bfloat16 g_klo[BB*HH*SQ*EE];
__device__ __nv_bfloat16 g_vthi[BB*HH*EE*SQ];  // [bh][e][s] (transposed)
__device__ __nv_bfloat16 g_vtlo[BB*HH*EE*SQ];

// ---------------------------------------------------------------------------
// Helpers
// ---------------------------------------------------------------------------
__device__ __forceinline__ void mma16816(float c[4],
    uint32_t a0, uint32_t a1, uint32_t a2, uint32_t a3,
    uint32_t b0, uint32_t b1)
{
    asm volatile(
        "mma.sync.aligned.m16n8k16.row.col.f32.bf16.bf16.f32 "
        "{%0,%1,%2,%3}, {%4,%5,%6,%7}, {%8,%9}, {%0,%1,%2,%3};"
        : "+f"(c[0]), "+f"(c[1]), "+f"(c[2]), "+f"(c[3])
        : "r"(a0), "r"(a1), "r"(a2), "r"(a3), "r"(b0), "r"(b1));
}
__device__ __forceinline__ void ldm_x4(uint32_t& r0, uint32_t& r1,
                                       uint32_t& r2, uint32_t& r3, uint32_t addr)
{
    asm volatile("ldmatrix.sync.aligned.m8n8.x4.shared.b16 {%0,%1,%2,%3}, [%4];"
        : "=r"(r0), "=r"(r1), "=r"(r2), "=r"(r3) : "r"(addr));
}
__device__ __forceinline__ void cpasync16(uint32_t dst, const void* src) {
    asm volatile("cp.async.cg.shared.global [%0], [%1], 16;"
        :: "r"(dst), "l"(src) : "memory");
}
#define CP_COMMIT() asm volatile("cp.async.commit_group;" ::: "memory")
#define CP_WAIT1()  asm volatile("cp.async.wait_group 1;" ::: "memory")
#define CP_WAIT0()  asm volatile("cp.async.wait_group 0;" ::: "memory")

__device__ __forceinline__ float ex2(float x) {
    float r; asm("ex2.approx.ftz.f32 %0, %1;" : "=f"(r) : "f"(x)); return r;
}
__device__ __forceinline__ uint32_t pack_hi(float a, float b, float& ra, float& rb) {
    __nv_bfloat162 h = __floats2bfloat162_rn(a, b);
    ra = a - __low2float(h); rb = b - __high2float(h);
    return *(uint32_t*)&h;
}
__device__ __forceinline__ uint32_t pack_bf(float a, float b) {
    __nv_bfloat162 h = __floats2bfloat162_rn(a, b);
    return *(uint32_t*)&h;
}

// ---------------------------------------------------------------------------
// bf16x3 mma.sync GEMM core: ldmatrix fragments + cp.async double buffer
// ---------------------------------------------------------------------------
#define PITCH 40
#define PLANE (128 * PITCH)            // halfwords per plane
#define GSTAGE (4 * PLANE)             // halfwords per stage
#define GEMM_DYN_BYTES (2 * GSTAGE * 2)   // 81920

extern __shared__ __nv_bfloat16 dyn_smem[];

__device__ __forceinline__ void tc_gemm_mma(
    const __nv_bfloat16* __restrict__ Ahi, const __nv_bfloat16* __restrict__ Alo,
    const __nv_bfloat16* __restrict__ Bhi, const __nv_bfloat16* __restrict__ Blo,
    int m0, int n0, float c[4][4][4])
{
    const int tid = threadIdx.x;
    const int wid = tid >> 5, lane = tid & 31;
    const int wm = wid & 1, wn = wid >> 1;
    const int sel = lane >> 3, r8 = lane & 7;

    #pragma unroll
    for (int i = 0; i < 4; i++)
        #pragma unroll
        for (int j = 0; j < 4; j++)
            #pragma unroll
            for (int t = 0; t < 4; t++) c[i][j][t] = 0.f;

    const uint32_t sbase = (uint32_t)__cvta_generic_to_shared(dyn_smem);
    const __nv_bfloat16* planes[4] = {Ahi, Alo, Bhi, Blo};

    auto prefetch = [&](int kc, int buf) {
        const int k0 = kc * 32;
        #pragma unroll
        for (int p = 0; p < 4; p++) {
            const __nv_bfloat16* src = planes[p];
            const int br = (p < 2) ? m0 : n0;
            const uint32_t dplane = sbase + (uint32_t)(buf * GSTAGE + p * PLANE) * 2;
            #pragma unroll
            for (int i = 0; i < 2; i++) {
                const int idx = i * 256 + tid;        // [0,512)
                const int row = idx >> 2, seg = idx & 3;
                cpasync16(dplane + (uint32_t)(row * PITCH + seg * 8) * 2,
                          src + (size_t)(br + row) * 1024 + k0 + seg * 8);
            }
        }
        CP_COMMIT();
    };

    prefetch(0, 0);
    prefetch(1, 1);

    for (int kc = 0; kc < 32; kc++) {
        const int buf = kc & 1;
        if (kc == 31) { CP_WAIT0(); } else { CP_WAIT1(); }
        __syncthreads();

        const uint32_t ab  = sbase + (uint32_t)(buf * GSTAGE) * 2;
        const uint32_t pAh = ab;
        const uint32_t pAl = ab + (uint32_t)PLANE * 2;
        const uint32_t pBh = ab + (uint32_t)(2 * PLANE) * 2;
        const uint32_t pBl = ab + (uint32_t)(3 * PLANE) * 2;

        #pragma unroll
        for (int k16 = 0; k16 < 2; k16++) {
            const int kb = k16 * 16;
            uint32_t aH[4][4], aL[4][4], bH[2][4], bL[2][4];
            #pragma unroll
            for (int i = 0; i < 4; i++) {
                const uint32_t off = (uint32_t)((wm * 64 + i * 16 + r8 + (sel & 1) * 8) * PITCH
                                                + kb + (sel >> 1) * 8) * 2;
                ldm_x4(aH[i][0], aH[i][1], aH[i][2], aH[i][3], pAh + off);
                ldm_x4(aL[i][0], aL[i][1], aL[i][2], aL[i][3], pAl + off);
            }
            #pragma unroll
            for (int jp = 0; jp < 2; jp++) {
                const uint32_t off = (uint32_t)(((wn * 32 + (jp * 2 + (sel >> 1)) * 8) + r8) * PITCH
                                                + kb + (sel & 1) * 8) * 2;
                ldm_x4(bH[jp][0], bH[jp][1], bH[jp][2], bH[jp][3], pBh + off);
                ldm_x4(bL[jp][0], bL[jp][1], bL[jp][2], bL[jp][3], pBl + off);
            }
            #pragma unroll
            for (int i = 0; i < 4; i++)
                #pragma unroll
                for (int j = 0; j < 4; j++) {
                    const uint32_t b0h = bH[j >> 1][(j & 1) * 2];
                    const uint32_t b1h = bH[j >> 1][(j & 1) * 2 + 1];
                    const uint32_t b0l = bL[j >> 1][(j & 1) * 2];
                    const uint32_t b1l = bL[j >> 1][(j & 1) * 2 + 1];
                    mma16816(c[i][j], aH[i][0], aH[i][1], aH[i][2], aH[i][3], b0h, b1h);
                    mma16816(c[i][j], aH[i][0], aH[i][1], aH[i][2], aH[i][3], b0l, b1l);
                    mma16816(c[i][j], aL[i][0], aL[i][1], aL[i][2], aL[i][3], b0h, b1h);
                }
        }
        __syncthreads();
        if (kc + 2 < 32) prefetch(kc + 2, buf);
    }
}

// ---------------------------------------------------------------------------
// QKV GEMM: epilogue writes pre-scaled bf16-split q, k (seq offset 2048),
// v transposed — exactly the layouts the attention kernel consumes.
// ---------------------------------------------------------------------------
__global__ __launch_bounds__(256) void qkv_mma_kernel(const float* __restrict__ bias)
{
    const int m0 = blockIdx.y * 128, n0 = blockIdx.x * 128;
    float c[4][4][4];
    tc_gemm_mma(g_xhi, g_xlo, g_wqkv_hi, g_wqkv_lo, m0, n0, c);

    const int tid = threadIdx.x, wid = tid >> 5, lane = tid & 31;
    const int wm = wid & 1, wn = wid >> 1;
    const int qr = lane >> 2, qc = lane & 3;

    #pragma unroll
    for (int i = 0; i < 4; i++) {
        #pragma unroll
        for (int j = 0; j < 4; j++) {
            const int n = n0 + wn * 32 + j * 8 + qc * 2;
            const int part = n >> 10;
            const int h = (n & 1023) >> 6;
            const int e = n & 63;
            const float b0 = bias[n], b1 = bias[n + 1];
            #pragma unroll
            for (int half = 0; half < 2; half++) {
                const int m = m0 + wm * 64 + i * 16 + qr + half * 8;
                const int bb = m >> 9, t = m & 511;
                const int bh = bb * HH + h;
                float v0 = c[i][j][half * 2] + b0;
                float v1 = c[i][j][half * 2 + 1] + b1;
                if (part == 0) {
                    v0 *= QSCALE; v1 *= QSCALE;
                    float l0, l1;
                    uint32_t hi = pack_hi(v0, v1, l0, l1);
                    uint32_t lo = pack_bf(l0, l1);
                    size_t off = ((size_t)bh * TT + t) * 64 + e;
                    *(uint32_t*)(g_qhi + off) = hi;
                    *(uint32_t*)(g_qlo + off) = lo;
                } else if (part == 1) {
                    float l0, l1;
                    uint32_t hi = pack_hi(v0, v1, l0, l1);
                    uint32_t lo = pack_bf(l0, l1);
                    size_t off = ((size_t)bh * SQ + LL + t) * 64 + e;
                    *(uint32_t*)(g_khi + off) = hi;
                    *(uint32_t*)(g_klo + off) = lo;
                } else {
                    __nv_bfloat16 h0 = __float2bfloat16_rn(v0);
                    __nv_bfloat16 h1 = __float2bfloat16_rn(v1);
                    __nv_bfloat16 l0 = __float2bfloat16_rn(v0 - __bfloat162float(h0));
                    __nv_bfloat16 l1 = __float2bfloat16_rn(v1 - __bfloat162float(h1));
                    size_t o0 = ((size_t)bh * 64 + e) * SQ + LL + t;
                    size_t o1 = ((size_t)bh * 64 + e + 1) * SQ + LL + t;
                    g_vthi[o0] = h0; g_vtlo[o0] = l0;
                    g_vthi[o1] = h1; g_vtlo[o1] = l1;
                }
            }
        }
    }
}

// ---------------------------------------------------------------------------
// Proj GEMM
// ---------------------------------------------------------------------------
__global__ __launch_bounds__(256) void proj_mma_kernel(const float* __restrict__ bias,
                                                       float* __restrict__ out)
{
    const int m0 = blockIdx.y * 128, n0 = blockIdx.x * 128;
    float c[4][4][4];
    tc_gemm_mma(g_yhi, g_ylo, g_wp_hi, g_wp_lo, m0, n0, c);

    const int tid = threadIdx.x, wid = tid >> 5, lane = tid & 31;
    const int wm = wid & 1, wn = wid >> 1;
    const int qr = lane >> 2, qc = lane & 3;

    #pragma unroll
    for (int i = 0; i < 4; i++) {
        #pragma unroll
        for (int j = 0; j < 4; j++) {
            const int n = n0 + wn * 32 + j * 8 + qc * 2;
            const float b0 = bias[n], b1 = bias[n + 1];
            #pragma unroll
            for (int half = 0; half < 2; half++) {
                const int m = m0 + wm * 64 + i * 16 + qr + half * 8;
                float2 w = make_float2(c[i][j][half * 2] + b0,
                                       c[i][j][half * 2 + 1] + b1);
                *(float2*)&out[(size_t)m * 1024 + n] = w;
            }
        }
    }
}

// ---------------------------------------------------------------------------
// Flash attention: ldmatrix fragments + cp.async double-buffered K/V tiles
// ---------------------------------------------------------------------------
#define APITCH 72
#define APLANE (64 * APITCH)           // halfwords per array
#define ASTAGE (4 * APLANE)            // Kh,Kl,Vh,Vl
#define ATT_DYN_BYTES (2 * ASTAGE * 2) // 73728

__global__ __launch_bounds__(256) void attn_mma_kernel()
{
    const int tid = threadIdx.x, wid = tid >> 5, lane = tid & 31;
    const int l4 = lane >> 2, qn = lane & 3;
    const int sel = lane >> 3, r8 = lane & 7;
    const int bh = blockIdx.y;
    const int qb = 3 - blockIdx.x;
    const int base = qb * 128;

    const uint32_t sbase = (uint32_t)__cvta_generic_to_shared(dyn_smem);

    // Persistent Q fragments (pre-scaled bf16 hi/lo) — straight from gmem
    uint32_t aQh[4][4], aQl[4][4];
    {
        const __nv_bfloat16* qh = g_qhi + ((size_t)bh * TT + base + wid * 16) * 64;
        const __nv_bfloat16* ql = g_qlo + ((size_t)bh * TT + base + wid * 16) * 64;
        #pragma unroll
        for (int kk = 0; kk < 4; kk++) {
            const int c0 = kk * 16 + qn * 2;
            aQh[kk][0] = *(const uint32_t*)(qh + l4 * 64 + c0);
            aQh[kk][1] = *(const uint32_t*)(qh + (l4 + 8) * 64 + c0);
            aQh[kk][2] = *(const uint32_t*)(qh + l4 * 64 + c0 + 8);
            aQh[kk][3] = *(const uint32_t*)(qh + (l4 + 8) * 64 + c0 + 8);
            aQl[kk][0] = *(const uint32_t*)(ql + l4 * 64 + c0);
            aQl[kk][1] = *(const uint32_t*)(ql + (l4 + 8) * 64 + c0);
            aQl[kk][2] = *(const uint32_t*)(ql + l4 * 64 + c0 + 8);
            aQl[kk][3] = *(const uint32_t*)(ql + (l4 + 8) * 64 + c0 + 8);
        }
    }

    float O[8][4];
    #pragma unroll
    for (int j = 0; j < 8; j++)
        #pragma unroll
        for (int t = 0; t < 4; t++) O[j][t] = 0.f;
    float mrow[2] = {-1e30f, -1e30f};
    float lrow[2] = {0.f, 0.f};

    const __nv_bfloat16* Kh  = g_khi  + (size_t)bh * SQ * 64;
    const __nv_bfloat16* Kl  = g_klo  + (size_t)bh * SQ * 64;
    const __nv_bfloat16* Vth = g_vthi + (size_t)bh * 64 * SQ;
    const __nv_bfloat16* Vtl = g_vtlo + (size_t)bh * 64 * SQ;

    const int n_tiles = 32 + 2 * (qb + 1);

    auto prefetch = [&](int kt, int buf) {
        const int s0 = kt * 64;
        const uint32_t dst = sbase + (uint32_t)(buf * ASTAGE) * 2;
        #pragma unroll
        for (int i = 0; i < 2; i++) {
            const int idx = i * 256 + tid;        // [0,512)
            const int row = idx >> 3, seg = idx & 7;
            const uint32_t doff = (uint32_t)(row * APITCH + seg * 8) * 2;
            cpasync16(dst + doff,
                      Kh + (size_t)(s0 + row) * 64 + seg * 8);
            cpasync16(dst + (uint32_t)APLANE * 2 + doff,
                      Kl + (size_t)(s0 + row) * 64 + seg * 8);
            cpasync16(dst + (uint32_t)(2 * APLANE) * 2 + doff,
                      Vth + (size_t)row * SQ + s0 + seg * 8);
            cpasync16(dst + (uint32_t)(3 * APLANE) * 2 + doff,
                      Vtl + (size_t)row * SQ + s0 + seg * 8);
        }
        CP_COMMIT();
    };

    prefetch(0, 0);
    if (n_tiles > 1) prefetch(1, 1);

    for (int kt = 0; kt < n_tiles; kt++) {
        const int buf = kt & 1;
        if (kt >= n_tiles - 1) { CP_WAIT0(); } else { CP_WAIT1(); }
        __syncthreads();

        const uint32_t ab  = sbase + (uint32_t)(buf * ASTAGE) * 2;
        const uint32_t pKh = ab;
        const uint32_t pKl = ab + (uint32_t)APLANE * 2;
        const uint32_t pVh = ab + (uint32_t)(2 * APLANE) * 2;
        const uint32_t pVl = ab + (uint32_t)(3 * APLANE) * 2;
        const int s0 = kt * 64;

        // S = Q K^T (bf16x3)
        float Sc[8][4];
        #pragma unroll
        for (int j = 0; j < 8; j++)
            #pragma unroll
            for (int t = 0; t < 4; t++) Sc[j][t] = 0.f;

        #pragma unroll
        for (int kk = 0; kk < 4; kk++) {
            #pragma unroll
            for (int jp = 0; jp < 4; jp++) {
                const uint32_t off = (uint32_t)(((jp * 2 + (sel >> 1)) * 8 + r8) * APITCH
                                                + kk * 16 + (sel & 1) * 8) * 2;
                uint32_t kh[4], kl[4];
                ldm_x4(kh[0], kh[1], kh[2], kh[3], pKh + off);
                ldm_x4(kl[0], kl[1], kl[2], kl[3], pKl + off);
                #pragma unroll
                for (int jj = 0; jj < 2; jj++) {
                    const int j = jp * 2 + jj;
                    mma16816(Sc[j], aQh[kk][0], aQh[kk][1], aQh[kk][2], aQh[kk][3],
                             kh[jj * 2], kh[jj * 2 + 1]);
                    mma16816(Sc[j], aQh[kk][0], aQh[kk][1], aQh[kk][2], aQh[kk][3],
                             kl[jj * 2], kl[jj * 2 + 1]);
                    mma16816(Sc[j], aQl[kk][0], aQl[kk][1], aQl[kk][2], aQl[kk][3],
                             kh[jj * 2], kh[jj * 2 + 1]);
                }
            }
        }

        // Causal mask (block-local query row)
        if (kt >= n_tiles - 2) {
            const int lim = s0 - LL - base;
            #pragma unroll
            for (int j = 0; j < 8; j++)
                #pragma unroll
                for (int t = 0; t < 4; t++) {
                    const int col = j * 8 + qn * 2 + (t & 1);
                    const int row = wid * 16 + l4 + ((t >> 1) << 3);
                    if (col + lim > row) Sc[j][t] = -1e30f;
                }
        }

        // Online softmax (per row-half; 4-lane shfl reductions)
        #pragma unroll
        for (int h = 0; h < 2; h++) {
            float mt = -1e30f;
            #pragma unroll
            for (int j = 0; j < 8; j++)
                mt = fmaxf(mt, fmaxf(Sc[j][2 * h], Sc[j][2 * h + 1]));
            mt = fmaxf(mt, __shfl_xor_sync(0xffffffffu, mt, 1));
            mt = fmaxf(mt, __shfl_xor_sync(0xffffffffu, mt, 2));
            const float mn = fmaxf(mrow[h], mt);
            const float alpha = ex2(mrow[h] - mn);
            mrow[h] = mn;
            float ls = 0.f;
            #pragma unroll
            for (int j = 0; j < 8; j++) {
                float p0 = ex2(Sc[j][2 * h] - mn);
                float p1 = ex2(Sc[j][2 * h + 1] - mn);
                Sc[j][2 * h] = p0; Sc[j][2 * h + 1] = p1;
                ls += p0 + p1;
            }
            ls += __shfl_xor_sync(0xffffffffu, ls, 1);
            ls += __shfl_xor_sync(0xffffffffu, ls, 2);
            lrow[h] = lrow[h] * alpha + ls;
            #pragma unroll
            for (int j = 0; j < 8; j++) {
                O[j][2 * h] *= alpha; O[j][2 * h + 1] *= alpha;
            }
        }

        // Pack P -> A fragments
        uint32_t aPh[4][4], aPl[4][4];
        #pragma unroll
        for (int kk = 0; kk < 4; kk++) {
            const int j0 = 2 * kk, j1 = 2 * kk + 1;
            float l0, l1;
            aPh[kk][0] = pack_hi(Sc[j0][0], Sc[j0][1], l0, l1);
            aPl[kk][0] = pack_bf(l0, l1);
            aPh[kk][1] = pack_hi(Sc[j0][2], Sc[j0][3], l0, l1);
            aPl[kk][1] = pack_bf(l0, l1);
            aPh[kk][2] = pack_hi(Sc[j1][0], Sc[j1][1], l0, l1);
            aPl[kk][2] = pack_bf(l0, l1);
            aPh[kk][3] = pack_hi(Sc[j1][2], Sc[j1][3], l0, l1);
            aPl[kk][3] = pack_bf(l0, l1);
        }

        // O += P V (bf16x3; V^T as B)
        #pragma unroll
        for (int kk = 0; kk < 4; kk++) {
            #pragma unroll
            for (int jp = 0; jp < 4; jp++) {
                const uint32_t off = (uint32_t)(((jp * 2 + (sel >> 1)) * 8 + r8) * APITCH
                                                + kk * 16 + (sel & 1) * 8) * 2;
                uint32_t vh[4], vl[4];
                ldm_x4(vh[0], vh[1], vh[2], vh[3], pVh + off);
                ldm_x4(vl[0], vl[1], vl[2], vl[3], pVl + off);
                #pragma unroll
                for (int jj = 0; jj < 2; jj++) {
                    const int j = jp * 2 + jj;
                    mma16816(O[j], aPh[kk][0], aPh[kk][1], aPh[kk][2], aPh[kk][3],
                             vh[jj * 2], vh[jj * 2 + 1]);
                    mma16816(O[j], aPh[kk][0], aPh[kk][1], aPh[kk][2], aPh[kk][3],
                             vl[jj * 2], vl[jj * 2 + 1]);
                    mma16816(O[j], aPl[kk][0], aPl[kk][1], aPl[kk][2], aPl[kk][3],
                             vh[jj * 2], vh[jj * 2 + 1]);
                }
            }
        }

        __syncthreads();
        if (kt + 2 < n_tiles) prefetch(kt + 2, buf);
    }

    // Epilogue: y = O / l -> bf16-split proj input
    const int b = bh >> 4, hh = bh & 15;
    #pragma unroll
    for (int h = 0; h < 2; h++) {
        const int t = base + wid * 16 + l4 + h * 8;
        const float inv = 1.f / lrow[h];
        #pragma unroll
        for (int j = 0; j < 8; j++) {
            const float y0 = O[j][2 * h] * inv;
            const float y1 = O[j][2 * h + 1] * inv;
            float l0, l1;
            uint32_t hi = pack_hi(y0, y1, l0, l1);
            uint32_t lo = pack_bf(l0, l1);
            const size_t off = ((size_t)(b * TT + t)) * CC + hh * 64 + j * 8 + qn * 2;
            *(uint32_t*)(g_yhi + off) = hi;
            *(uint32_t*)(g_ylo + off) = lo;
        }
    }
}

// ---------------------------------------------------------------------------
// Prep kernels (unchanged)
// ---------------------------------------------------------------------------
__global__ __launch_bounds__(256) void split_kernel(const float* __restrict__ in,
                                                    __nv_bfloat16* __restrict__ hi,
                                                    __nv_bfloat16* __restrict__ lo,
                                                    int n4)
{
    int i = blockIdx.x * 256 + threadIdx.x;
    if (i >= n4) return;
    float4 v = ((const float4*)in)[i];
    __nv_bfloat16 h[4], l[4];
    float a[4] = {v.x, v.y, v.z, v.w};
    #pragma unroll
    for (int j = 0; j < 4; j++) {
        h[j] = __float2bfloat16_rn(a[j]);
        l[j] = __float2bfloat16_rn(a[j] - __bfloat162float(h[j]));
    }
    ((uint2*)hi)[i] = *(uint2*)h;
    ((uint2*)lo)[i] = *(uint2*)l;
}

__global__ __launch_bounds__(256) void tsplit_kernel(const float* __restrict__ W,
                                                     __nv_bfloat16* __restrict__ hi,
                                                     __nv_bfloat16* __restrict__ lo,
                                                     int K, int N)
{
    __shared__ float tile[32][33];
    const int nx = blockIdx.x * 32, kx = blockIdx.y * 32;
    const int tx = threadIdx.x, ty = threadIdx.y;
    #pragma unroll
    for (int r = ty; r < 32; r += 8)
        tile[r][tx] = W[(size_t)(kx + r) * N + nx + tx];
    __syncthreads();
    #pragma unroll
    for (int r = ty; r < 32; r += 8) {
        float x = tile[tx][r];
        __nv_bfloat16 h = __float2bfloat16_rn(x);
        __nv_bfloat16 l = __float2bfloat16_rn(x - __bfloat162float(h));
        size_t o = (size_t)(nx + r) * K + kx + tx;
        hi[o] = h;
        lo[o] = l;
    }
}

__global__ __launch_bounds__(256) void kcache_prep(const float* __restrict__ kc)
{
    const size_t i = (size_t)blockIdx.x * 256 + threadIdx.x;
    float4 v = ((const float4*)kc)[i];
    const size_t flat = i * 4;
    const size_t bh = flat >> 17;
    const size_t rem = flat & 131071;
    const size_t s = rem >> 6, e = rem & 63;
    __nv_bfloat16 h[4], l[4];
    float a[4] = {v.x, v.y, v.z, v.w};
    #pragma unroll
    for (int j = 0; j < 4; j++) {
        h[j] = __float2bfloat16_rn(a[j]);
        l[j] = __float2bfloat16_rn(a[j] - __bfloat162float(h[j]));
    }
    const size_t off = (bh * SQ + s) * 64 + e;
    *(uint2*)(g_khi + off) = *(uint2*)h;
    *(uint2*)(g_klo + off) = *(uint2*)l;
}

__global__ void vcache_prep(const float* __restrict__ vc)
{
    __shared__ float tile[32][33];
    const int bh = blockIdx.z;
    const int s0 = blockIdx.x * 32, e0 = blockIdx.y * 32;
    const int tx = threadIdx.x, ty = threadIdx.y;
    #pragma unroll
    for (int r = ty; r < 32; r += 8)
        tile[r][tx] = vc[((size_t)bh * LL + s0 + r) * 64 + e0 + tx];
    __syncthreads();
    #pragma unroll
    for (int r = ty; r < 32; r += 8) {
        float x = tile[tx][r];
        __nv_bfloat16 h = __float2bfloat16_rn(x);
        __nv_bfloat16 l = __float2bfloat16_rn(x - __bfloat162float(h));
        const size_t off = ((size_t)bh * 64 + e0 + r) * SQ + s0 + tx;
        g_vthi[off] = h;
        g_vtlo[off] = l;
    }
}

// ---------------------------------------------------------------------------
extern "C" void kernel_launch(void* const* d_in, const int* in_sizes, int n_in,
                              void* d_out, int out_size) {
    const float* x       = (const float*)d_in[0];
    const float* k_cache = (const float*)d_in[1];
    const float* v_cache = (const float*)d_in[2];
    const float* Wqkv    = (const float*)d_in[3];
    const float* bqkv    = (const float*)d_in[4];
    const float* Wproj   = (const float*)d_in[5];
    const float* bproj   = (const float*)d_in[6];
    float* out           = (float*)d_out;

    cudaFuncSetAttribute(qkv_mma_kernel, cudaFuncAttributeMaxDynamicSharedMemorySize,
                         GEMM_DYN_BYTES);
    cudaFuncSetAttribute(proj_mma_kernel, cudaFuncAttributeMaxDynamicSharedMemorySize,
                         GEMM_DYN_BYTES);
    cudaFuncSetAttribute(attn_mma_kernel, cudaFuncAttributeMaxDynamicSharedMemorySize,
                         ATT_DYN_BYTES);

    __nv_bfloat16 *xhi, *xlo, *wqh, *wql, *wph, *wpl;
    cudaGetSymbolAddress((void**)&xhi, g_xhi);
    cudaGetSymbolAddress((void**)&xlo, g_xlo);
    cudaGetSymbolAddress((void**)&wqh, g_wqkv_hi);
    cudaGetSymbolAddress((void**)&wql, g_wqkv_lo);
    cudaGetSymbolAddress((void**)&wph, g_wp_hi);
    cudaGetSymbolAddress((void**)&wpl, g_wp_lo);

    split_kernel<<<4096, 256>>>(x, xhi, xlo, BB*TT*CC/4);
    tsplit_kernel<<<dim3(96, 32), dim3(32, 8)>>>(Wqkv, wqh, wql, 1024, 3072);
    tsplit_kernel<<<dim3(32, 32), dim3(32, 8)>>>(Wproj, wph, wpl, 1024, 1024);
    kcache_prep<<<16384, 256>>>(k_cache);
    vcache_prep<<<dim3(64, 2, 128), dim3(32, 8)>>>(v_cache);

    qkv_mma_kernel<<<dim3(24, 32), 256, GEMM_DYN_BYTES>>>(bqkv);
    attn_mma_kernel<<<dim3(4, 128), 256, ATT_DYN_BYTES>>>();
    proj_mma_kernel<<<dim3(8, 32), 256, GEMM_DYN_BYTES>>>(bproj, out);
}